// round 4
// baseline (speedup 1.0000x reference)
#include <cuda_runtime.h>
#include <cstdint>
#include <cstddef>

#define BATCH 2
#define NN    1000
#define EE    2000
#define HH    128
#define BE    (BATCH*EE)   // 4000
#define BN    (BATCH*NN)   // 2000
#define SPLITK 4

__device__ float g_Z[BE*HH];
__device__ float g_Ypart[SPLITK][BE*HH];
__device__ float g_norm[BN];
__device__ float g_Ttf[HH*HH*HH];   // edge_network pre-rounded to tf32 (8 MB)

__device__ __forceinline__ uint32_t f2tf(float x) {
    uint32_t r; asm("cvt.rna.tf32.f32 %0, %1;" : "=r"(r) : "f"(x)); return r;
}
__device__ __forceinline__ float f2tff(float x) { return __uint_as_float(f2tf(x)); }

__device__ __forceinline__ void mma8(float c[4],
                                     uint32_t a0, uint32_t a1, uint32_t a2, uint32_t a3,
                                     uint32_t b0, uint32_t b1) {
    asm volatile(
        "mma.sync.aligned.m16n8k8.row.col.f32.tf32.tf32.f32 "
        "{%0,%1,%2,%3}, {%4,%5,%6,%7}, {%8,%9}, {%0,%1,%2,%3};\n"
        : "+f"(c[0]), "+f"(c[1]), "+f"(c[2]), "+f"(c[3])
        : "r"(a0), "r"(a1), "r"(a2), "r"(a3), "r"(b0), "r"(b1));
}

__device__ __forceinline__ void cp16(float* smem_dst, const float* gsrc) {
    uint32_t s = (uint32_t)__cvta_generic_to_shared(smem_dst);
    asm volatile("cp.async.cg.shared.global [%0], [%1], 16;\n" :: "r"(s), "l"(gsrc));
}
__device__ __forceinline__ void cp_commit() { asm volatile("cp.async.commit_group;\n"); }
__device__ __forceinline__ void cp_wait0()  { asm volatile("cp.async.wait_group 0;\n"); }

// ---------------------------------------------------------------------------
__global__ void convert_T_kernel(const float* __restrict__ en) {
    int i = blockIdx.x * 256 + threadIdx.x;
    float4 v = ((const float4*)en)[i];
    ((float4*)g_Ttf)[i] = make_float4(f2tff(v.x), f2tff(v.y), f2tff(v.z), f2tff(v.w));
}

// ---------------------------------------------------------------------------
// Kernel 1: Z = node2edge @ node_state.  Tile 64(e) x 128(h), k-chunks 32.
// 8 warps = 2(M) x 4(N), per-warp 32x32. grid (32, 2) = 64 CTAs.
// ---------------------------------------------------------------------------
__global__ __launch_bounds__(256, 2)
void gemm1_kernel(const float* __restrict__ n2e, const float* __restrict__ ns) {
    __shared__ float As[64][36];
    __shared__ float Bs[32][136];
    const int tid = threadIdx.x, lane = tid & 31, warp = tid >> 5;
    const int gid = lane >> 2, tig = lane & 3;
    const int wrow = (warp & 1) * 32, wcol = (warp >> 1) * 32;
    const int b = blockIdx.y, e0 = blockIdx.x * 64;
    const int rows = min(64, EE - e0);
    const float* Ag = n2e + (size_t)b * EE * NN;
    const float* Bg = ns  + (size_t)b * NN * HH;
    float acc[2][4][4] = {};
    const int NC = (NN + 31) / 32;   // 32

    float4 ar[2], br[4];
    auto ldA = [&](int c) {
        int k0 = c * 32, kv = NN - k0;
        #pragma unroll
        for (int i = 0; i < 2; i++) {
            int lin = tid + i * 256, r = lin >> 3, c4 = (lin & 7) * 4;
            ar[i] = make_float4(0.f,0.f,0.f,0.f);
            if (r < rows && c4 < kv) ar[i] = *(const float4*)(Ag + (size_t)(e0 + r) * NN + k0 + c4);
        }
    };
    auto ldB = [&](int c) {
        int k0 = c * 32, kv = NN - k0;
        #pragma unroll
        for (int i = 0; i < 4; i++) {
            int lin = tid + i * 256, kk = lin >> 5, c4 = (lin & 31) * 4;
            br[i] = make_float4(0.f,0.f,0.f,0.f);
            if (kk < kv) br[i] = *(const float4*)(Bg + (size_t)(k0 + kk) * HH + c4);
        }
    };
    ldA(0); ldB(0);

    for (int c = 0; c < NC; c++) {
        __syncthreads();
        #pragma unroll
        for (int i = 0; i < 2; i++) {
            int lin = tid + i * 256, r = lin >> 3, c4 = (lin & 7) * 4;
            As[r][c4+0]=f2tff(ar[i].x); As[r][c4+1]=f2tff(ar[i].y);
            As[r][c4+2]=f2tff(ar[i].z); As[r][c4+3]=f2tff(ar[i].w);
        }
        #pragma unroll
        for (int i = 0; i < 4; i++) {
            int lin = tid + i * 256, kk = lin >> 5, c4 = (lin & 31) * 4;
            Bs[kk][c4+0]=f2tff(br[i].x); Bs[kk][c4+1]=f2tff(br[i].y);
            Bs[kk][c4+2]=f2tff(br[i].z); Bs[kk][c4+3]=f2tff(br[i].w);
        }
        __syncthreads();
        if (c + 1 < NC) { ldA(c + 1); ldB(c + 1); }
        #pragma unroll
        for (int ks = 0; ks < 4; ks++) {
            const int kb = ks * 8;
            uint32_t a[2][4];
            #pragma unroll
            for (int mt = 0; mt < 2; mt++) {
                int r0 = wrow + mt * 16 + gid;
                a[mt][0] = __float_as_uint(As[r0    ][kb+tig  ]);
                a[mt][1] = __float_as_uint(As[r0 + 8][kb+tig  ]);
                a[mt][2] = __float_as_uint(As[r0    ][kb+tig+4]);
                a[mt][3] = __float_as_uint(As[r0 + 8][kb+tig+4]);
            }
            #pragma unroll
            for (int nt = 0; nt < 4; nt++) {
                int colb = wcol + nt * 8 + gid;
                uint32_t b0 = __float_as_uint(Bs[kb+tig  ][colb]);
                uint32_t b1 = __float_as_uint(Bs[kb+tig+4][colb]);
                mma8(acc[0][nt], a[0][0],a[0][1],a[0][2],a[0][3], b0,b1);
                mma8(acc[1][nt], a[1][0],a[1][1],a[1][2],a[1][3], b0,b1);
            }
        }
    }
    #pragma unroll
    for (int mt = 0; mt < 2; mt++)
        #pragma unroll
        for (int nt = 0; nt < 4; nt++) {
            int col = wcol + nt * 8 + tig * 2;
            int r0 = wrow + mt * 16 + gid, r1 = r0 + 8;
            if (r0 < rows) { float* p = g_Z + ((size_t)(b*EE + e0 + r0))*HH + col; p[0]=acc[mt][nt][0]; p[1]=acc[mt][nt][1]; }
            if (r1 < rows) { float* p = g_Z + ((size_t)(b*EE + e0 + r1))*HH + col; p[0]=acc[mt][nt][2]; p[1]=acc[mt][nt][3]; }
        }
}

// ---------------------------------------------------------------------------
// Main kernel: Y[r,i] = sum_{h,j} X[r,h]*T[h,i,j]*Z[r,j].
// 64 rows x 128 i; split-K over h (4 x 32). grid (63, 4) = 252 CTAs, 2/SM.
// 8 warps = 2(M) x 4(N), per-warp 32 rows x 32 i.
// ---------------------------------------------------------------------------
#define XS_E (64*36)
#define ZS_E (64*132)
#define TB_E (128*36)
#define MAIN_SMEM ((XS_E + ZS_E + 2*TB_E) * 4)   // 79872 B

__global__ __launch_bounds__(256, 2)
void gemm_main_kernel(const float* __restrict__ ev) {
    extern __shared__ float sm[];
    float* Xs = sm;               // [64][36]  raw fp32 (32 h-cols)
    float* Zs = sm + XS_E;        // [64][132] raw fp32
    float* Tb = Zs + ZS_E;        // 2 x [128][36] tf32 bits

    const int tid = threadIdx.x, lane = tid & 31, warp = tid >> 5;
    const int gid = lane >> 2, tig = lane & 3;
    const int wrow = (warp & 1) * 32, wcol = (warp >> 1) * 32;
    const int row0 = blockIdx.x * 64, rows = min(64, BE - row0);
    const int h0 = blockIdx.y * 32;

    // prefetch T chunk 0 (h=h0, j0=0): 128 x 32 floats
    {
        const float* src = g_Ttf + (size_t)h0 * (HH*HH);
        #pragma unroll
        for (int i = 0; i < 4; i++) {
            int lin = tid + i * 256, ir = lin >> 3, c4 = (lin & 7) * 4;
            cp16(Tb + ir*36 + c4, src + ir*HH + c4);
        }
        cp_commit();
    }
    // preload Xs (rows x 32) and Zs (rows x 128)
    #pragma unroll
    for (int i = 0; i < 2; i++) {
        int lin = tid + i * 256, r = lin >> 3, c4 = (lin & 7) * 4;
        float4 v = make_float4(0.f,0.f,0.f,0.f);
        if (r < rows) v = *(const float4*)(ev + (size_t)(row0 + r) * HH + h0 + c4);
        Xs[r*36+c4+0]=v.x; Xs[r*36+c4+1]=v.y; Xs[r*36+c4+2]=v.z; Xs[r*36+c4+3]=v.w;
    }
    #pragma unroll
    for (int i = 0; i < 8; i++) {
        int lin = tid + i * 256, r = lin >> 5, c4 = (lin & 31) * 4;
        float4 v = make_float4(0.f,0.f,0.f,0.f);
        if (r < rows) v = *(const float4*)(g_Z + (size_t)(row0 + r) * HH + c4);
        Zs[r*132+c4+0]=v.x; Zs[r*132+c4+1]=v.y; Zs[r*132+c4+2]=v.z; Zs[r*132+c4+3]=v.w;
    }
    __syncthreads();

    const int R0 = wrow + gid;
    float acc[2][4][4] = {};
    int cc = 0;

    for (int j0i = 0; j0i < 4; j0i++) {
        const int j0 = j0i * 32;
        float zr[4][8];
        #pragma unroll
        for (int r = 0; r < 4; r++)
            #pragma unroll
            for (int q = 0; q < 8; q++)
                zr[r][q] = Zs[(R0 + r*8)*132 + j0 + tig + 4*q];

        #pragma unroll 1
        for (int hi = 0; hi < 32; hi++) {
            cp_wait0();
            __syncthreads();
            const int nx = cc + 1;
            if (nx < 128) {
                const int hn = nx & 31, j0n = (nx >> 5) * 32;
                const float* src = g_Ttf + (size_t)(h0 + hn) * (HH*HH) + j0n;
                float* dst = Tb + (nx & 1) * TB_E;
                #pragma unroll
                for (int i = 0; i < 4; i++) {
                    int lin = tid + i * 256, ir = lin >> 3, c4 = (lin & 7) * 4;
                    cp16(dst + ir*36 + c4, src + ir*HH + c4);
                }
            }
            cp_commit();

            const float* Bsb = Tb + (cc & 1) * TB_E;
            float xv0 = Xs[ R0      *36 + hi];
            float xv1 = Xs[(R0 +  8)*36 + hi];
            float xv2 = Xs[(R0 + 16)*36 + hi];
            float xv3 = Xs[(R0 + 24)*36 + hi];

            #pragma unroll
            for (int ks = 0; ks < 4; ks++) {
                const int kb = ks * 8;
                uint32_t a[2][4];
                a[0][0] = f2tf(xv0 * zr[0][2*ks  ]);
                a[0][1] = f2tf(xv1 * zr[1][2*ks  ]);
                a[0][2] = f2tf(xv0 * zr[0][2*ks+1]);
                a[0][3] = f2tf(xv1 * zr[1][2*ks+1]);
                a[1][0] = f2tf(xv2 * zr[2][2*ks  ]);
                a[1][1] = f2tf(xv3 * zr[3][2*ks  ]);
                a[1][2] = f2tf(xv2 * zr[2][2*ks+1]);
                a[1][3] = f2tf(xv3 * zr[3][2*ks+1]);
                #pragma unroll
                for (int nt = 0; nt < 4; nt++) {
                    int colb = wcol + nt * 8 + gid;
                    uint32_t b0 = __float_as_uint(Bsb[colb*36 + kb+tig  ]);
                    uint32_t b1 = __float_as_uint(Bsb[colb*36 + kb+tig+4]);
                    mma8(acc[0][nt], a[0][0],a[0][1],a[0][2],a[0][3], b0,b1);
                    mma8(acc[1][nt], a[1][0],a[1][1],a[1][2],a[1][3], b0,b1);
                }
            }
            cc++;
        }
    }

    float* Yp = g_Ypart[blockIdx.y];
    #pragma unroll
    for (int mt = 0; mt < 2; mt++)
        #pragma unroll
        for (int nt = 0; nt < 4; nt++) {
            int col = wcol + nt * 8 + tig * 2;
            int r0 = wrow + mt * 16 + gid, r1 = r0 + 8;
            if (r0 < rows) { float* p = Yp + (size_t)(row0+r0)*HH + col; p[0]=acc[mt][nt][0]; p[1]=acc[mt][nt][1]; }
            if (r1 < rows) { float* p = Yp + (size_t)(row0+r1)*HH + col; p[0]=acc[mt][nt][2]; p[1]=acc[mt][nt][3]; }
        }
}

// ---------------------------------------------------------------------------
__global__ void norm_kernel(const float* __restrict__ e2n) {
    int row = blockIdx.x * 8 + (threadIdx.x >> 5), lane = threadIdx.x & 31;
    const float* p = e2n + (size_t)row * EE;
    float s = 0.f;
    for (int e = lane; e < EE; e += 32) s += p[e];
    #pragma unroll
    for (int o = 16; o > 0; o >>= 1) s += __shfl_xor_sync(0xffffffffu, s, o);
    if (lane == 0) g_norm[row] = s + 1.0f;
}

// ---------------------------------------------------------------------------
// Kernel 3: out = (edge2node @ sum_p Ypart[p] + node_state) / norm.
// Tile 32(n) x 128(i), 8 warps = 2(M) x 4(N), per-warp 16x32.
// Split-K reduction fused into the B load. grid (32, 2) = 64 CTAs.
// ---------------------------------------------------------------------------
__global__ __launch_bounds__(256, 2)
void gemm3_kernel(const float* __restrict__ e2n, const float* __restrict__ ns,
                  float* __restrict__ out) {
    __shared__ float As[32][36];
    __shared__ float Bs[32][136];
    const int tid = threadIdx.x, lane = tid & 31, warp = tid >> 5;
    const int gid = lane >> 2, tig = lane & 3;
    const int wrow = (warp & 1) * 16, wcol = (warp >> 1) * 32;
    const int b = blockIdx.y, n0 = blockIdx.x * 32;
    const int rows = min(32, NN - n0);
    const float* Ag = e2n + ((size_t)b * NN + n0) * EE;
    const size_t Boff = (size_t)b * EE * HH;
    float acc[4][4] = {};
    const int NC = (EE + 31) / 32;   // 63

    float4 ar, br[4];
    auto ldA = [&](int c) {
        int k0 = c * 32, kv = EE - k0;
        int r = tid >> 3, c4 = (tid & 7) * 4;
        ar = make_float4(0.f,0.f,0.f,0.f);
        if (r < rows && c4 < kv) ar = *(const float4*)(Ag + (size_t)r * EE + k0 + c4);
    };
    auto ldB = [&](int c) {
        int k0 = c * 32, kv = EE - k0;
        #pragma unroll
        for (int i = 0; i < 4; i++) {
            int lin = tid + i * 256, kk = lin >> 5, c4 = (lin & 31) * 4;
            br[i] = make_float4(0.f,0.f,0.f,0.f);
            if (kk < kv) {
                size_t idx = Boff + (size_t)(k0 + kk) * HH + c4;
                #pragma unroll
                for (int p = 0; p < SPLITK; p++) {
                    float4 v = *(const float4*)(&g_Ypart[p][idx]);
                    br[i].x += v.x; br[i].y += v.y; br[i].z += v.z; br[i].w += v.w;
                }
            }
        }
    };
    ldA(0); ldB(0);

    for (int c = 0; c < NC; c++) {
        __syncthreads();
        {
            int r = tid >> 3, c4 = (tid & 7) * 4;
            As[r][c4+0]=f2tff(ar.x); As[r][c4+1]=f2tff(ar.y);
            As[r][c4+2]=f2tff(ar.z); As[r][c4+3]=f2tff(ar.w);
        }
        #pragma unroll
        for (int i = 0; i < 4; i++) {
            int lin = tid + i * 256, kk = lin >> 5, c4 = (lin & 31) * 4;
            Bs[kk][c4+0]=f2tff(br[i].x); Bs[kk][c4+1]=f2tff(br[i].y);
            Bs[kk][c4+2]=f2tff(br[i].z); Bs[kk][c4+3]=f2tff(br[i].w);
        }
        __syncthreads();
        if (c + 1 < NC) { ldA(c + 1); ldB(c + 1); }
        #pragma unroll
        for (int ks = 0; ks < 4; ks++) {
            const int kb = ks * 8;
            int r0 = wrow + gid;
            uint32_t a0 = __float_as_uint(As[r0    ][kb+tig  ]);
            uint32_t a1 = __float_as_uint(As[r0 + 8][kb+tig  ]);
            uint32_t a2 = __float_as_uint(As[r0    ][kb+tig+4]);
            uint32_t a3 = __float_as_uint(As[r0 + 8][kb+tig+4]);
            #pragma unroll
            for (int nt = 0; nt < 4; nt++) {
                int colb = wcol + nt * 8 + gid;
                uint32_t b0 = __float_as_uint(Bs[kb+tig  ][colb]);
                uint32_t b1 = __float_as_uint(Bs[kb+tig+4][colb]);
                mma8(acc[nt], a0, a1, a2, a3, b0, b1);
            }
        }
    }
    const float* nsb = ns + ((size_t)b * NN) * HH;
    #pragma unroll
    for (int nt = 0; nt < 4; nt++) {
        int col = wcol + nt * 8 + tig * 2;
        int r0 = wrow + gid, r1 = r0 + 8;
        if (r0 < rows) {
            size_t idx = (size_t)(n0 + r0) * HH + col;
            float nv = g_norm[b*NN + n0 + r0];
            float* po = out + (size_t)b * NN * HH + idx;
            po[0] = (acc[nt][0] + nsb[idx  ]) / nv;
            po[1] = (acc[nt][1] + nsb[idx+1]) / nv;
        }
        if (r1 < rows) {
            size_t idx = (size_t)(n0 + r1) * HH + col;
            float nv = g_norm[b*NN + n0 + r1];
            float* po = out + (size_t)b * NN * HH + idx;
            po[0] = (acc[nt][2] + nsb[idx  ]) / nv;
            po[1] = (acc[nt][3] + nsb[idx+1]) / nv;
        }
    }
}

// ---------------------------------------------------------------------------
extern "C" void kernel_launch(void* const* d_in, const int* in_sizes, int n_in,
                              void* d_out, int out_size) {
    const float* node_state = (const float*)d_in[0];
    const float* edge_vec   = (const float*)d_in[1];
    const float* node2edge  = (const float*)d_in[2];
    const float* edge2node  = (const float*)d_in[3];
    const float* edge_net   = (const float*)d_in[4];
    float* out = (float*)d_out;

    cudaFuncSetAttribute(gemm_main_kernel,
                         cudaFuncAttributeMaxDynamicSharedMemorySize, MAIN_SMEM);

    convert_T_kernel<<<(HH*HH*HH)/4/256, 256>>>(edge_net);
    gemm1_kernel<<<dim3(32, 2), 256>>>(node2edge, node_state);
    norm_kernel<<<250, 256>>>(edge2node);
    gemm_main_kernel<<<dim3(63, SPLITK), 256, MAIN_SMEM>>>(edge_vec);
    gemm3_kernel<<<dim3(32, 2), 256>>>(edge2node, node_state, out);
}

// round 5
// speedup vs baseline: 1.3716x; 1.3716x over previous
#include <cuda_runtime.h>
#include <cstdint>
#include <cstddef>

#define BATCH 2
#define NN    1000
#define EE    2000
#define HH    128
#define BE    (BATCH*EE)   // 4000
#define BN    (BATCH*NN)   // 2000
#define SPLITK 4

__device__ float g_Z[BE*HH];
__device__ float g_Ypart[SPLITK][BE*HH];
__device__ float g_Y[BE*HH];
__device__ float g_Tp[HH*HH*HH];   // T pre-rounded to tf32, pair-permuted (8 MB)

__device__ __forceinline__ uint32_t f2tf(float x) {
    uint32_t r; asm("cvt.rna.tf32.f32 %0, %1;" : "=r"(r) : "f"(x)); return r;
}
__device__ __forceinline__ float f2tff(float x) { return __uint_as_float(f2tf(x)); }

__device__ __forceinline__ void mma8(float c[4],
                                     uint32_t a0, uint32_t a1, uint32_t a2, uint32_t a3,
                                     uint32_t b0, uint32_t b1) {
    asm volatile(
        "mma.sync.aligned.m16n8k8.row.col.f32.tf32.tf32.f32 "
        "{%0,%1,%2,%3}, {%4,%5,%6,%7}, {%8,%9}, {%0,%1,%2,%3};\n"
        : "+f"(c[0]), "+f"(c[1]), "+f"(c[2]), "+f"(c[3])
        : "r"(a0), "r"(a1), "r"(a2), "r"(a3), "r"(b0), "r"(b1));
}

__device__ __forceinline__ void cp16(float* smem_dst, const float* gsrc) {
    uint32_t s = (uint32_t)__cvta_generic_to_shared(smem_dst);
    asm volatile("cp.async.cg.shared.global [%0], [%1], 16;\n" :: "r"(s), "l"(gsrc));
}
__device__ __forceinline__ void cp_commit() { asm volatile("cp.async.commit_group;\n"); }
__device__ __forceinline__ void cp_wait2()  { asm volatile("cp.async.wait_group 2;\n"); }

// ---------------------------------------------------------------------------
// convert: g_Tp = tf32(T), with j-permutation inside each 8-group:
// pos(j) = (j & ~7) + 2*(j&3) + ((j>>2)&1), so (j, j+4) become adjacent.
// ---------------------------------------------------------------------------
__global__ void convert_T_kernel(const float* __restrict__ en) {
    int i = blockIdx.x * 256 + threadIdx.x;     // float4 index
    float4 v = ((const float4*)en)[i];
    int base = i * 4;
    int row = base >> 7;        // (h,i) row, 128 j per row
    int j   = base & 127;      // multiple of 4 -> j&7 in {0,4}
    float* dst = g_Tp + ((size_t)row << 7) + (j & ~7);
    if ((j & 4) == 0) {
        dst[0] = f2tff(v.x); dst[2] = f2tff(v.y); dst[4] = f2tff(v.z); dst[6] = f2tff(v.w);
    } else {
        dst[1] = f2tff(v.x); dst[3] = f2tff(v.y); dst[5] = f2tff(v.z); dst[7] = f2tff(v.w);
    }
}

// ---------------------------------------------------------------------------
// Kernel 1: Z = node2edge @ node_state. Tile 32(e) x 128(h), grid (63,2)=126.
// 8 warps, each 32 rows x 16 cols.
// ---------------------------------------------------------------------------
__global__ __launch_bounds__(256, 2)
void gemm1_kernel(const float* __restrict__ n2e, const float* __restrict__ ns) {
    __shared__ float As[32][36];
    __shared__ float Bs[32][136];
    const int tid = threadIdx.x, lane = tid & 31, warp = tid >> 5;
    const int gid = lane >> 2, tig = lane & 3;
    const int wcol = warp * 16;
    const int b = blockIdx.y, e0 = blockIdx.x * 32;
    const int rows = min(32, EE - e0);
    const float* Ag = n2e + (size_t)b * EE * NN;
    const float* Bg = ns  + (size_t)b * NN * HH;
    float acc[2][2][4] = {};
    const int NC = (NN + 31) / 32;   // 32

    float4 ar, br[4];
    auto ldA = [&](int c) {
        int k0 = c * 32, kv = NN - k0;
        int r = tid >> 3, c4 = (tid & 7) * 4;
        ar = make_float4(0.f,0.f,0.f,0.f);
        if (r < rows && c4 < kv) ar = *(const float4*)(Ag + (size_t)(e0 + r) * NN + k0 + c4);
    };
    auto ldB = [&](int c) {
        int k0 = c * 32, kv = NN - k0;
        #pragma unroll
        for (int i = 0; i < 4; i++) {
            int lin = tid + i * 256, kk = lin >> 5, c4 = (lin & 31) * 4;
            br[i] = make_float4(0.f,0.f,0.f,0.f);
            if (kk < kv) br[i] = *(const float4*)(Bg + (size_t)(k0 + kk) * HH + c4);
        }
    };
    ldA(0); ldB(0);

    for (int c = 0; c < NC; c++) {
        __syncthreads();
        {
            int r = tid >> 3, c4 = (tid & 7) * 4;
            As[r][c4+0]=f2tff(ar.x); As[r][c4+1]=f2tff(ar.y);
            As[r][c4+2]=f2tff(ar.z); As[r][c4+3]=f2tff(ar.w);
        }
        #pragma unroll
        for (int i = 0; i < 4; i++) {
            int lin = tid + i * 256, kk = lin >> 5, c4 = (lin & 31) * 4;
            Bs[kk][c4+0]=f2tff(br[i].x); Bs[kk][c4+1]=f2tff(br[i].y);
            Bs[kk][c4+2]=f2tff(br[i].z); Bs[kk][c4+3]=f2tff(br[i].w);
        }
        __syncthreads();
        if (c + 1 < NC) { ldA(c + 1); ldB(c + 1); }
        #pragma unroll
        for (int ks = 0; ks < 4; ks++) {
            const int kb = ks * 8;
            uint32_t a[2][4];
            #pragma unroll
            for (int mt = 0; mt < 2; mt++) {
                int r0 = mt * 16 + gid;
                a[mt][0] = __float_as_uint(As[r0    ][kb+tig  ]);
                a[mt][1] = __float_as_uint(As[r0 + 8][kb+tig  ]);
                a[mt][2] = __float_as_uint(As[r0    ][kb+tig+4]);
                a[mt][3] = __float_as_uint(As[r0 + 8][kb+tig+4]);
            }
            #pragma unroll
            for (int nt = 0; nt < 2; nt++) {
                int colb = wcol + nt * 8 + gid;
                uint32_t b0 = __float_as_uint(Bs[kb+tig  ][colb]);
                uint32_t b1 = __float_as_uint(Bs[kb+tig+4][colb]);
                mma8(acc[0][nt], a[0][0],a[0][1],a[0][2],a[0][3], b0,b1);
                mma8(acc[1][nt], a[1][0],a[1][1],a[1][2],a[1][3], b0,b1);
            }
        }
    }
    #pragma unroll
    for (int mt = 0; mt < 2; mt++)
        #pragma unroll
        for (int nt = 0; nt < 2; nt++) {
            int col = wcol + nt * 8 + tig * 2;
            int r0 = mt * 16 + gid, r1 = r0 + 8;
            if (r0 < rows) { float* p = g_Z + ((size_t)(b*EE + e0 + r0))*HH + col; p[0]=acc[mt][nt][0]; p[1]=acc[mt][nt][1]; }
            if (r1 < rows) { float* p = g_Z + ((size_t)(b*EE + e0 + r1))*HH + col; p[0]=acc[mt][nt][2]; p[1]=acc[mt][nt][3]; }
        }
}

// ---------------------------------------------------------------------------
// Main kernel: Y[r,i] = sum_{h,j} X[r,h]*T[h,i,j]*Z[r,j].
// 64 rows x 128 i; split-K over h (4 x 32). grid (63,4)=252, 2 CTAs/SM.
// 4-stage cp.async pipeline on T chunks; B frags via LDS.64 (permuted T).
// ---------------------------------------------------------------------------
#define XS_E (64*36)
#define TBS  (128*40)
#define MAIN_SMEM ((XS_E + 4*TBS) * 4)   // 91136 B

__global__ __launch_bounds__(256, 2)
void gemm_main_kernel(const float* __restrict__ ev) {
    extern __shared__ float sm[];
    float* Xs = sm;               // [64][36] raw fp32 (32 h-cols)
    float* Tb = sm + XS_E;        // 4 x [128][40] tf32 bits (pair-permuted)

    const int tid = threadIdx.x, lane = tid & 31, warp = tid >> 5;
    const int gid = lane >> 2, tig = lane & 3;
    const int wrow = (warp & 1) * 32, wcol = (warp >> 1) * 32;
    const int row0 = blockIdx.x * 64, rows = min(64, BE - row0);
    const int h0 = blockIdx.y * 32;

    auto issueT = [&](int c) {
        const int hn = c & 31, j0n = (c >> 5) * 32;
        const float* src = g_Tp + (size_t)(h0 + hn) * (HH*HH) + j0n;
        float* dst = Tb + (c & 3) * TBS;
        #pragma unroll
        for (int i = 0; i < 4; i++) {
            int lin = tid + i * 256, ir = lin >> 3, c4 = (lin & 7) * 4;
            cp16(dst + ir*40 + c4, src + (size_t)ir*HH + c4);
        }
    };
    issueT(0); cp_commit();
    issueT(1); cp_commit();
    issueT(2); cp_commit();

    // Xs: rows x 32 h-cols, raw fp32
    #pragma unroll
    for (int i = 0; i < 2; i++) {
        int lin = tid + i * 256, r = lin >> 3, c4 = (lin & 7) * 4;
        float4 v = make_float4(0.f,0.f,0.f,0.f);
        if (r < rows) v = *(const float4*)(ev + (size_t)(row0 + r) * HH + h0 + c4);
        Xs[r*36+c4+0]=v.x; Xs[r*36+c4+1]=v.y; Xs[r*36+c4+2]=v.z; Xs[r*36+c4+3]=v.w;
    }
    __syncthreads();

    const int R0 = wrow + gid;
    float acc[2][4][4] = {};

    for (int j0i = 0; j0i < 4; j0i++) {
        const int j0 = j0i * 32;
        // Z fragments straight from GMEM (4 rows x 8 j-positions per thread)
        float zr[4][8];
        #pragma unroll
        for (int r = 0; r < 4; r++) {
            int grow = row0 + R0 + 8*r;
            if (grow < BE) {
                const float* zp = g_Z + (size_t)grow * HH + j0 + tig;
                #pragma unroll
                for (int q = 0; q < 8; q++) zr[r][q] = zp[4*q];
            } else {
                #pragma unroll
                for (int q = 0; q < 8; q++) zr[r][q] = 0.f;
            }
        }

        #pragma unroll 1
        for (int hi = 0; hi < 32; hi++) {
            const int cc = j0i * 32 + hi;
            cp_wait2();
            __syncthreads();
            if (cc + 3 < 128) issueT(cc + 3);
            cp_commit();

            const float* Bsb = Tb + (cc & 3) * TBS;
            float xv0 = Xs[ R0      *36 + hi];
            float xv1 = Xs[(R0 +  8)*36 + hi];
            float xv2 = Xs[(R0 + 16)*36 + hi];
            float xv3 = Xs[(R0 + 24)*36 + hi];

            #pragma unroll
            for (int ks = 0; ks < 4; ks++) {
                const int kb = ks * 8;
                uint32_t a00 = f2tf(xv0 * zr[0][2*ks  ]);
                uint32_t a01 = f2tf(xv1 * zr[1][2*ks  ]);
                uint32_t a02 = f2tf(xv0 * zr[0][2*ks+1]);
                uint32_t a03 = f2tf(xv1 * zr[1][2*ks+1]);
                uint32_t a10 = f2tf(xv2 * zr[2][2*ks  ]);
                uint32_t a11 = f2tf(xv3 * zr[3][2*ks  ]);
                uint32_t a12 = f2tf(xv2 * zr[2][2*ks+1]);
                uint32_t a13 = f2tf(xv3 * zr[3][2*ks+1]);
                #pragma unroll
                for (int nt = 0; nt < 4; nt++) {
                    int colb = wcol + nt * 8 + gid;
                    float2 bv = *(const float2*)(Bsb + colb*40 + kb + 2*tig);
                    uint32_t b0 = __float_as_uint(bv.x);
                    uint32_t b1 = __float_as_uint(bv.y);
                    mma8(acc[0][nt], a00,a01,a02,a03, b0,b1);
                    mma8(acc[1][nt], a10,a11,a12,a13, b0,b1);
                }
            }
        }
    }

    float* Yp = g_Ypart[blockIdx.y];
    #pragma unroll
    for (int mt = 0; mt < 2; mt++)
        #pragma unroll
        for (int nt = 0; nt < 4; nt++) {
            int col = wcol + nt * 8 + tig * 2;
            int r0 = wrow + mt * 16 + gid, r1 = r0 + 8;
            if (r0 < rows) { float* p = Yp + (size_t)(row0+r0)*HH + col; p[0]=acc[mt][nt][0]; p[1]=acc[mt][nt][1]; }
            if (r1 < rows) { float* p = Yp + (size_t)(row0+r1)*HH + col; p[0]=acc[mt][nt][2]; p[1]=acc[mt][nt][3]; }
        }
}

// ---------------------------------------------------------------------------
__global__ void reduce_kernel() {
    int i0 = (blockIdx.x * 256 + threadIdx.x) * 8;
    #pragma unroll
    for (int half = 0; half < 2; half++) {
        int idx = i0 + half * 4;
        float4 a = *(const float4*)&g_Ypart[0][idx];
        float4 b = *(const float4*)&g_Ypart[1][idx];
        float4 c = *(const float4*)&g_Ypart[2][idx];
        float4 d = *(const float4*)&g_Ypart[3][idx];
        *(float4*)&g_Y[idx] = make_float4(a.x+b.x+c.x+d.x, a.y+b.y+c.y+d.y,
                                          a.z+b.z+c.z+d.z, a.w+b.w+c.w+d.w);
    }
}

// ---------------------------------------------------------------------------
// Kernel 3: out = (edge2node @ Y + node_state) / (1 + rowsum(edge2node)).
// Tile 16(n) x 128(i), grid (63,2)=126 CTAs. Norm fused into A loads.
// 8 warps, each 16 rows x 16 cols.
// ---------------------------------------------------------------------------
__global__ __launch_bounds__(256, 2)
void gemm3_kernel(const float* __restrict__ e2n, const float* __restrict__ ns,
                  float* __restrict__ out) {
    __shared__ float As[16][36];
    __shared__ float Bs[32][136];
    __shared__ float nsp[128];
    __shared__ float nv_s[16];
    const int tid = threadIdx.x, lane = tid & 31, warp = tid >> 5;
    const int gid = lane >> 2, tig = lane & 3;
    const int wcol = warp * 16;
    const int b = blockIdx.y, n0 = blockIdx.x * 16;
    const int rows = min(16, NN - n0);
    const float* Ag = e2n + ((size_t)b * NN + n0) * EE;
    const float* Bg = g_Y + (size_t)b * EE * HH;
    float acc[2][4] = {};
    float asum = 0.f;
    const int NC = (EE + 31) / 32;   // 63

    float4 ar, br[4];
    auto ldA = [&](int c) {
        int k0 = c * 32, kv = EE - k0;
        int r = tid >> 3, c4 = (tid & 7) * 4;
        ar = make_float4(0.f,0.f,0.f,0.f);
        if (r < rows && c4 < kv && tid < 128)
            ar = *(const float4*)(Ag + (size_t)r * EE + k0 + c4);
        asum += ar.x + ar.y + ar.z + ar.w;
    };
    auto ldB = [&](int c) {
        int k0 = c * 32, kv = EE - k0;
        #pragma unroll
        for (int i = 0; i < 4; i++) {
            int lin = tid + i * 256, kk = lin >> 5, c4 = (lin & 31) * 4;
            br[i] = make_float4(0.f,0.f,0.f,0.f);
            if (kk < kv) br[i] = *(const float4*)(Bg + (size_t)(k0 + kk) * HH + c4);
        }
    };
    ldA(0); ldB(0);

    for (int c = 0; c < NC; c++) {
        __syncthreads();
        if (tid < 128) {
            int r = tid >> 3, c4 = (tid & 7) * 4;
            As[r][c4+0]=f2tff(ar.x); As[r][c4+1]=f2tff(ar.y);
            As[r][c4+2]=f2tff(ar.z); As[r][c4+3]=f2tff(ar.w);
        }
        #pragma unroll
        for (int i = 0; i < 4; i++) {
            int lin = tid + i * 256, kk = lin >> 5, c4 = (lin & 31) * 4;
            Bs[kk][c4+0]=f2tff(br[i].x); Bs[kk][c4+1]=f2tff(br[i].y);
            Bs[kk][c4+2]=f2tff(br[i].z); Bs[kk][c4+3]=f2tff(br[i].w);
        }
        __syncthreads();
        if (c + 1 < NC) { ldA(c + 1); ldB(c + 1); }
        #pragma unroll
        for (int ks = 0; ks < 4; ks++) {
            const int kb = ks * 8;
            uint32_t a0 = __float_as_uint(As[gid    ][kb+tig  ]);
            uint32_t a1 = __float_as_uint(As[gid + 8][kb+tig  ]);
            uint32_t a2 = __float_as_uint(As[gid    ][kb+tig+4]);
            uint32_t a3 = __float_as_uint(As[gid + 8][kb+tig+4]);
            #pragma unroll
            for (int nt = 0; nt < 2; nt++) {
                int colb = wcol + nt * 8 + gid;
                uint32_t b0 = __float_as_uint(Bs[kb+tig  ][colb]);
                uint32_t b1 = __float_as_uint(Bs[kb+tig+4][colb]);
                mma8(acc[nt], a0, a1, a2, a3, b0, b1);
            }
        }
    }
    // norm reduction: 8 partials per row
    if (tid < 128) nsp[tid] = asum;
    __syncthreads();
    if (tid < 16) {
        float s = 1.f;
        #pragma unroll
        for (int k = 0; k < 8; k++) s += nsp[tid*8 + k];
        nv_s[tid] = s;
    }
    __syncthreads();

    const float* nsb = ns + ((size_t)b * NN) * HH;
    #pragma unroll
    for (int nt = 0; nt < 2; nt++) {
        int col = wcol + nt * 8 + tig * 2;
        int r0 = gid, r1 = gid + 8;
        if (r0 < rows) {
            size_t idx = (size_t)(n0 + r0) * HH + col;
            float nv = nv_s[r0];
            float* po = out + (size_t)b * NN * HH + idx;
            po[0] = (acc[nt][0] + nsb[idx  ]) / nv;
            po[1] = (acc[nt][1] + nsb[idx+1]) / nv;
        }
        if (r1 < rows) {
            size_t idx = (size_t)(n0 + r1) * HH + col;
            float nv = nv_s[r1];
            float* po = out + (size_t)b * NN * HH + idx;
            po[0] = (acc[nt][2] + nsb[idx  ]) / nv;
            po[1] = (acc[nt][3] + nsb[idx+1]) / nv;
        }
    }
}

// ---------------------------------------------------------------------------
extern "C" void kernel_launch(void* const* d_in, const int* in_sizes, int n_in,
                              void* d_out, int out_size) {
    const float* node_state = (const float*)d_in[0];
    const float* edge_vec   = (const float*)d_in[1];
    const float* node2edge  = (const float*)d_in[2];
    const float* edge2node  = (const float*)d_in[3];
    const float* edge_net   = (const float*)d_in[4];
    float* out = (float*)d_out;

    cudaFuncSetAttribute(gemm_main_kernel,
                         cudaFuncAttributeMaxDynamicSharedMemorySize, MAIN_SMEM);

    convert_T_kernel<<<(HH*HH*HH)/4/256, 256>>>(edge_net);
    gemm1_kernel<<<dim3(63, 2), 256>>>(node2edge, node_state);
    gemm_main_kernel<<<dim3(63, SPLITK), 256, MAIN_SMEM>>>(edge_vec);
    reduce_kernel<<<250, 256>>>();
    gemm3_kernel<<<dim3(63, 2), 256>>>(edge2node, node_state, out);
}